// round 10
// baseline (speedup 1.0000x reference)
#include <cuda_runtime.h>
#include <cuda_fp16.h>
#include <cstdint>

// ---------------- problem constants ----------------
#define NN   16384      // nodes
#define EE   262144     // edges
#define DD   512        // embed dim
#define HH   8          // heads
#define HID  1024       // mlp hidden
#define MLPIN 536       // D + 3*H
#define MLPIN_P 544     // padded to /32

// ---------------- device scratch (no allocations allowed) ----------------
__device__ __half g_zh[(size_t)NN * DD];          // LN(att) fp16
__device__ __half g_mlpinh[(size_t)NN * MLPIN_P]; // [z_mlp | feat | 0pad] fp16
__device__ __half g_hidh[(size_t)NN * HID];       // gelu(hidden) fp16
__device__ __half g_qkh[(size_t)NN * 2 * DD];     // [q | k] fp16 per node
__device__ __half g_wqkh[(size_t)2 * DD * DD];    // [Wq; Wk] fp16
__device__ __half g_winh[(size_t)HID * MLPIN_P];
__device__ __half g_wouth[(size_t)DD * HID];
__device__ float g_bqk[2 * DD];
__device__ float g_biasT[(size_t)EE * HH];        // att_bias transposed [E,H]
__device__ int   g_cnt[NN];                       // edges per row
__device__ int   g_off[NN + 1];                   // exclusive prefix
__device__ int   g_cur[NN];                       // scatter cursor
__device__ int   g_eidx[EE];                      // edge ids bucketed by row

// ---------------- helpers ----------------
__device__ __forceinline__ uint32_t smem_u32(const void* p) {
    uint32_t a;
    asm("{ .reg .u64 t; cvta.to.shared.u64 t, %1; cvt.u32.u64 %0, t; }" : "=r"(a) : "l"(p));
    return a;
}
__device__ __forceinline__ float gelu_tanh(float v) {
    float u = 0.7978845608028654f * (v + 0.044715f * v * v * v);
    return 0.5f * v * (1.0f + tanhf(u));
}
__device__ __forceinline__ void ldsm_x4(uint32_t& r0, uint32_t& r1, uint32_t& r2, uint32_t& r3,
                                        uint32_t addr) {
    asm volatile("ldmatrix.sync.aligned.m8n8.x4.shared.b16 {%0,%1,%2,%3}, [%4];"
                 : "=r"(r0), "=r"(r1), "=r"(r2), "=r"(r3) : "r"(addr));
}
__device__ __forceinline__ void mma16816(float* c, const uint32_t* a, const uint32_t* b) {
    asm volatile("mma.sync.aligned.m16n8k16.row.col.f32.f16.f16.f32 "
                 "{%0,%1,%2,%3},{%4,%5,%6,%7},{%8,%9},{%0,%1,%2,%3};"
                 : "+f"(c[0]), "+f"(c[1]), "+f"(c[2]), "+f"(c[3])
                 : "r"(a[0]), "r"(a[1]), "r"(a[2]), "r"(a[3]), "r"(b[0]), "r"(b[1]));
}
__device__ __forceinline__ void cp16(uint32_t dst, const void* src) {
    asm volatile("cp.async.cg.shared.global [%0], [%1], 16;" :: "r"(dst), "l"(src));
}
#define CP_COMMIT() asm volatile("cp.async.commit_group;" ::: "memory")
#define CP_WAIT1()  asm volatile("cp.async.wait_group 1;" ::: "memory")
#define CP_WAIT0()  asm volatile("cp.async.wait_group 0;" ::: "memory")

// ---------------- fused prep: weight cvts + bias concat + count zero ----------------
#define PR0 (DD * DD)                     // Wq
#define PR1 (PR0 + DD * DD)               // Wk
#define PR2 (PR1 + HID * MLPIN_P)         // W_in padded
#define PR3 (PR2 + DD * HID)              // W_out
#define PR4 (PR3 + 2 * DD)                // bias cat
#define PR5 (PR4 + NN)                    // counts
__global__ void k_prep(const float* __restrict__ Wq, const float* __restrict__ Wk,
                       const float* __restrict__ W_in, const float* __restrict__ W_out,
                       const float* __restrict__ bq, const float* __restrict__ bk) {
    int t = blockIdx.x * blockDim.x + threadIdx.x;
    if (t < PR0) {
        g_wqkh[t] = __float2half(Wq[t]);
    } else if (t < PR1) {
        g_wqkh[t] = __float2half(Wk[t - PR0]);
    } else if (t < PR2) {
        int i = t - PR1;
        int r = i / MLPIN_P, c = i % MLPIN_P;
        g_winh[i] = (c < MLPIN) ? __float2half(W_in[(size_t)r * MLPIN + c]) : __half(0.0f);
    } else if (t < PR3) {
        int i = t - PR2;
        g_wouth[i] = __float2half(W_out[i]);
    } else if (t < PR4) {
        int i = t - PR3;
        g_bqk[i] = (i < DD) ? bq[i] : bk[i - DD];
    } else if (t < PR5) {
        g_cnt[t - PR4] = 0;
    }
}

// ---------------- att_bias transpose [H,E] -> [E,H] ----------------
__global__ void k_tr_bias(const float* __restrict__ ab) {
    __shared__ float tile[HH][33];
    int e0 = blockIdx.x * 32;
    int t = threadIdx.x;
    int h = t >> 5, i = t & 31;
    tile[h][i] = ab[(size_t)h * EE + e0 + i];
    __syncthreads();
    int e = t >> 3, hh = t & 7;
    g_biasT[(size_t)(e0 + e) * HH + hh] = tile[hh][e];
}

// ---------------- edge bucketing: histogram, scan, scatter ----------------
__global__ void k_hist(const int* __restrict__ row_index) {
    int t = blockIdx.x * blockDim.x + threadIdx.x;
    if (t < EE) atomicAdd(&g_cnt[row_index[t]], 1);
}
// single block, 1024 threads, 16 values each
__global__ void k_scan() {
    __shared__ int wsum[32];
    int t = threadIdx.x;
    int vals[16];
    int s = 0;
#pragma unroll
    for (int i = 0; i < 16; i++) { vals[i] = g_cnt[t * 16 + i]; s += vals[i]; }
    int lane = t & 31, wid = t >> 5;
    int x = s;
#pragma unroll
    for (int o = 1; o < 32; o <<= 1) {
        int y = __shfl_up_sync(0xffffffffu, x, o);
        if (lane >= o) x += y;
    }
    if (lane == 31) wsum[wid] = x;
    __syncthreads();
    if (wid == 0) {
        int v = wsum[lane];
#pragma unroll
        for (int o = 1; o < 32; o <<= 1) {
            int y = __shfl_up_sync(0xffffffffu, v, o);
            if (lane >= o) v += y;
        }
        wsum[lane] = v;
    }
    __syncthreads();
    int base = (wid > 0 ? wsum[wid - 1] : 0) + x - s;   // exclusive for this thread
    int run = base;
#pragma unroll
    for (int i = 0; i < 16; i++) {
        g_off[t * 16 + i] = run;
        g_cur[t * 16 + i] = run;
        run += vals[i];
    }
    if (t == 1023) g_off[NN] = run;
}
__global__ void k_scatter(const int* __restrict__ row_index) {
    int t = blockIdx.x * blockDim.x + threadIdx.x;
    if (t < EE) {
        int p = atomicAdd(&g_cur[row_index[t]], 1);
        g_eidx[p] = t;
    }
}

// ---------------- fused double layernorm -> fp16 outputs ----------------
__global__ void k_ln(const float* __restrict__ x,
                     const float* __restrict__ ga, const float* __restrict__ ba,
                     const float* __restrict__ gm, const float* __restrict__ bm) {
    int n = blockIdx.x;
    int t = threadIdx.x;
    const float* xr = x + (size_t)n * DD;
    float v[4];
    float s = 0.0f, s2 = 0.0f;
#pragma unroll
    for (int i = 0; i < 4; i++) {
        v[i] = xr[t + 128 * i];
        s += v[i];
        s2 += v[i] * v[i];
    }
    __shared__ float shs[4], shs2[4];
#pragma unroll
    for (int o = 16; o > 0; o >>= 1) {
        s  += __shfl_xor_sync(0xffffffffu, s, o);
        s2 += __shfl_xor_sync(0xffffffffu, s2, o);
    }
    int w = t >> 5;
    if ((t & 31) == 0) { shs[w] = s; shs2[w] = s2; }
    __syncthreads();
    s  = shs[0] + shs[1] + shs[2] + shs[3];
    s2 = shs2[0] + shs2[1] + shs2[2] + shs2[3];
    float mu = s * (1.0f / DD);
    float var = s2 * (1.0f / DD) - mu * mu;
    float rstd = rsqrtf(var + 1e-5f);
#pragma unroll
    for (int i = 0; i < 4; i++) {
        int c = t + 128 * i;
        float zz = (v[i] - mu) * rstd;
        g_zh[(size_t)n * DD + c]          = __float2half(zz * ga[c] + ba[c]);
        g_mlpinh[(size_t)n * MLPIN_P + c] = __float2half(zz * gm[c] + bm[c]);
    }
}

// ---------------- HMMA GEMM (R4-proven config) ----------------
#define BM 128
#define LDT 40

template <int ACT, int RESID, int OUT16>
__global__ void __launch_bounds__(256, 2) hmma_gemm(
    const __half* __restrict__ A, const __half* __restrict__ Bw,
    const float* __restrict__ bias, const float* __restrict__ resid,
    float* __restrict__ Cf, __half* __restrict__ Ch, int K, int Nc) {
    __shared__ __half As[2][BM * LDT];
    __shared__ __half Bs[2][BM * LDT];
    const int t = threadIdx.x;
    const int lane = t & 31;
    const int w = t >> 5;
    const int wm = w >> 2;   // 0..1
    const int wn = w & 3;    // 0..3
    const __half* Ag = A  + (size_t)(blockIdx.y * 128) * K;
    const __half* Bg = Bw + (size_t)(blockIdx.x * 128) * K;
    const uint32_t sA = smem_u32(As);
    const uint32_t sB = smem_u32(Bs);

    float acc[4][4][4];
#pragma unroll
    for (int i = 0; i < 4; i++)
#pragma unroll
        for (int j = 0; j < 4; j++)
#pragma unroll
            for (int q = 0; q < 4; q++) acc[i][j][q] = 0.0f;

    const int nch = K >> 5;

#define LOAD_CHUNK(c, buf) do {                                                    \
        int _k0 = (c) << 5;                                                        \
        _Pragma("unroll")                                                          \
        for (int _s = 0; _s < 2; _s++) {                                           \
            int _seg = t + _s * 256;                                               \
            int _row = _seg >> 2, _sc = _seg & 3;                                  \
            uint32_t _off = (uint32_t)((buf) * BM * LDT + _row * LDT + _sc * 8) * 2;\
            cp16(sA + _off, Ag + (size_t)_row * K + _k0 + _sc * 8);                \
            cp16(sB + _off, Bg + (size_t)_row * K + _k0 + _sc * 8);                \
        }                                                                          \
        CP_COMMIT();                                                               \
    } while (0)

    LOAD_CHUNK(0, 0);
    for (int c = 0; c < nch; c++) {
        if (c + 1 < nch) { LOAD_CHUNK(c + 1, (c + 1) & 1); CP_WAIT1(); }
        else             { CP_WAIT0(); }
        __syncthreads();
        const int buf = c & 1;
        const uint32_t baseA = sA + (uint32_t)(buf * BM * LDT) * 2;
        const uint32_t baseB = sB + (uint32_t)(buf * BM * LDT) * 2;
#pragma unroll
        for (int ks = 0; ks < 2; ks++) {
            uint32_t a[4][4];
#pragma unroll
            for (int mf = 0; mf < 4; mf++) {
                int row = wm * 64 + mf * 16 + (lane & 15);
                int col = ks * 16 + (lane >> 4) * 8;
                ldsm_x4(a[mf][0], a[mf][1], a[mf][2], a[mf][3],
                        baseA + (uint32_t)(row * LDT + col) * 2);
            }
            uint32_t b[2][4];
#pragma unroll
            for (int nb = 0; nb < 2; nb++) {
                int row = wn * 32 + nb * 16 + (lane & 7) + ((lane >> 4) & 1) * 8;
                int col = ks * 16 + ((lane >> 3) & 1) * 8;
                ldsm_x4(b[nb][0], b[nb][1], b[nb][2], b[nb][3],
                        baseB + (uint32_t)(row * LDT + col) * 2);
            }
#pragma unroll
            for (int mf = 0; mf < 4; mf++)
#pragma unroll
                for (int nf = 0; nf < 4; nf++)
                    mma16816(acc[mf][nf], a[mf], &b[nf >> 1][(nf & 1) * 2]);
        }
        __syncthreads();
    }

    const int rBase = blockIdx.y * 128 + wm * 64 + (lane >> 2);
    const int cBase = blockIdx.x * 128 + wn * 32 + (lane & 3) * 2;
#pragma unroll
    for (int mf = 0; mf < 4; mf++) {
#pragma unroll
        for (int nf = 0; nf < 4; nf++) {
            const float* cc = acc[mf][nf];
            int col = cBase + nf * 8;
            float b0 = bias[col], b1 = bias[col + 1];
#pragma unroll
            for (int hf = 0; hf < 2; hf++) {
                int row = rBase + mf * 16 + hf * 8;
                float v0 = cc[hf * 2 + 0] + b0;
                float v1 = cc[hf * 2 + 1] + b1;
                if (ACT) { v0 = gelu_tanh(v0); v1 = gelu_tanh(v1); }
                if (RESID) {
                    const float2 r2 = *(const float2*)(resid + (size_t)row * Nc + col);
                    v0 += r2.x; v1 += r2.y;
                }
                if (OUT16) {
                    *(__half2*)(Ch + (size_t)row * Nc + col) = __floats2half2_rn(v0, v1);
                } else {
                    *(float2*)(Cf + (size_t)row * Nc + col) = make_float2(v0, v1);
                }
            }
        }
    }
#undef LOAD_CHUNK
}

// ---------------- row-bucketed edge pass: one warp per row, no atomics ----------
// q held in registers; den/rowsum/feat accumulate in registers at lanes 0-7;
// final normalize + pos-centering + fp16 mlpin-tail write fused here.
__global__ void k_row_edges(const int* __restrict__ src_index,
                            const int* __restrict__ org_to_src,
                            const float* __restrict__ dist,
                            const float* __restrict__ src_pos,
                            const float* __restrict__ pos) {
    int n = blockIdx.x * 8 + (threadIdx.x >> 5);
    int lane = threadIdx.x & 31;
    const __half2* qr2 = (const __half2*)(g_qkh + (size_t)n * (2 * DD));
    __half2 qreg[HH];
#pragma unroll
    for (int h = 0; h < HH; h++) qreg[h] = qr2[h * 32 + lane];
    float den = 0.f, rsum = 0.f, fx = 0.f, fy = 0.f, fz = 0.f;
    int e0 = g_off[n], e1 = g_off[n + 1];
    for (int e = e0; e < e1; e++) {
        int ei  = g_eidx[e];
        int si  = src_index[ei];
        int src = org_to_src[si];
        const __half2* kr2 = (const __half2*)(g_qkh + (size_t)src * (2 * DD) + DD);
        float cap = 0.f;
#pragma unroll
        for (int h = 0; h < HH; h++) {
            float2 qf = __half22float2(qreg[h]);
            float2 kf = __half22float2(kr2[h * 32 + lane]);
            float s = qf.x * kf.x + qf.y * kf.y;
#pragma unroll
            for (int o = 16; o > 0; o >>= 1) s += __shfl_xor_sync(0xffffffffu, s, o);
            if (lane == h) cap = s;
        }
        if (lane < HH) {
            float l = cap * 0.125f + g_biasT[(size_t)ei * HH + lane];
            float p = __expf(l);
            float d = dist[ei];
            float w = (d == 0.f) ? 0.f : p / d;
            float sx = src_pos[3 * si + 0];
            float sy = src_pos[3 * si + 1];
            float sz = src_pos[3 * si + 2];
            den += p; rsum += w;
            fx += w * sx; fy += w * sy; fz += w * sz;
        }
    }
    if (lane < HH) {
        float inv = (den != 0.f) ? 1.f / den : 0.f;
        float px = pos[n * 3 + 0], py = pos[n * 3 + 1], pz = pos[n * 3 + 2];
        __half* dst = g_mlpinh + (size_t)n * MLPIN_P + DD + lane * 3;
        dst[0] = __float2half(fx * inv - rsum * inv * px);
        dst[1] = __float2half(fy * inv - rsum * inv * py);
        dst[2] = __float2half(fz * inv - rsum * inv * pz);
    } else if (lane < 16) {
        g_mlpinh[(size_t)n * MLPIN_P + DD + 24 + (lane - 8)] = __half(0.0f);
    }
}

// ---------------- launch ----------------
extern "C" void kernel_launch(void* const* d_in, const int* in_sizes, int n_in,
                              void* d_out, int out_size) {
    const float* x        = (const float*)d_in[0];
    const float* Wq       = (const float*)d_in[1];
    const float* bq       = (const float*)d_in[2];
    const float* Wk       = (const float*)d_in[3];
    const float* bk       = (const float*)d_in[4];
    const float* g_att    = (const float*)d_in[5];
    const float* b_att    = (const float*)d_in[6];
    const float* g_mlp    = (const float*)d_in[7];
    const float* b_mlp    = (const float*)d_in[8];
    const float* W_in     = (const float*)d_in[9];
    const float* b_in     = (const float*)d_in[10];
    const float* W_out    = (const float*)d_in[11];
    const float* b_out    = (const float*)d_in[12];
    const float* att_bias = (const float*)d_in[13];
    const float* dist     = (const float*)d_in[14];
    const float* pos      = (const float*)d_in[15];
    const float* src_pos  = (const float*)d_in[16];
    const int*   row_index  = (const int*)d_in[17];
    const int*   src_index  = (const int*)d_in[18];
    const int*   org_to_src = (const int*)d_in[19];
    float* out = (float*)d_out;

    __half *pzh, *pmlpinh, *phidh, *pqkh, *pwqkh, *pwinh, *pwouth;
    float* pbqk;
    cudaGetSymbolAddress((void**)&pzh, g_zh);
    cudaGetSymbolAddress((void**)&pmlpinh, g_mlpinh);
    cudaGetSymbolAddress((void**)&phidh, g_hidh);
    cudaGetSymbolAddress((void**)&pqkh, g_qkh);
    cudaGetSymbolAddress((void**)&pwqkh, g_wqkh);
    cudaGetSymbolAddress((void**)&pwinh, g_winh);
    cudaGetSymbolAddress((void**)&pwouth, g_wouth);
    cudaGetSymbolAddress((void**)&pbqk, g_bqk);

    k_prep<<<(PR5 + 255) / 256, 256>>>(Wq, Wk, W_in, W_out, bq, bk);
    k_tr_bias<<<EE / 32, 256>>>(att_bias);
    k_hist<<<EE / 256, 256>>>(row_index);
    k_scan<<<1, 1024>>>();
    k_scatter<<<EE / 256, 256>>>(row_index);
    k_ln<<<NN, 128>>>(x, g_att, b_att, g_mlp, b_mlp);
    // [q|k] = z @ [Wq;Wk]^T + [bq;bk]  -> fp16 [N, 1024]
    hmma_gemm<0, 0, 1><<<dim3(2 * DD / 128, NN / 128), 256>>>(
        pzh, pwqkh, pbqk, nullptr, nullptr, pqkh, DD, 2 * DD);
    k_row_edges<<<NN / 8, 256>>>(src_index, org_to_src, dist, src_pos, pos);
    // hid = gelu(mlpin @ W_in^T + b_in) -> fp16
    hmma_gemm<1, 0, 1><<<dim3(HID / 128, NN / 128), 256>>>(
        pmlpinh, pwinh, b_in, nullptr, nullptr, phidh, MLPIN_P, HID);
    // out = x + hid @ W_out^T + b_out -> fp32
    hmma_gemm<0, 1, 0><<<dim3(DD / 128, NN / 128), 256>>>(
        phidh, pwouth, b_out, x, out, nullptr, HID, DD);
}

// round 12
// speedup vs baseline: 1.2272x; 1.2272x over previous
#include <cuda_runtime.h>
#include <cuda_fp16.h>
#include <cstdint>

// ---------------- problem constants ----------------
#define NN   16384      // nodes
#define EE   262144     // edges
#define DD   512        // embed dim
#define HH   8          // heads
#define HID  1024       // mlp hidden
#define MLPIN 536       // D + 3*H
#define MLPIN_P 544     // padded to /32

// ---------------- device scratch (no allocations allowed) ----------------
__device__ __half g_zh[(size_t)NN * DD];          // LN(att) fp16
__device__ __half g_mlpinh[(size_t)NN * MLPIN_P]; // [z_mlp | feat | 0pad] fp16
__device__ __half g_hidh[(size_t)NN * HID];       // gelu(hidden) fp16
__device__ __half g_qkh[(size_t)NN * 2 * DD];     // [q | k] fp16 per node
__device__ __half g_wqkh[(size_t)2 * DD * DD];    // [Wq; Wk] fp16
__device__ __half g_winh[(size_t)HID * MLPIN_P];
__device__ __half g_wouth[(size_t)DD * HID];
__device__ float g_bqk[2 * DD];
__device__ float g_biasT[(size_t)EE * HH];        // att_bias transposed [E,H]
__device__ float g_den[(size_t)NN * HH];
__device__ float g_rowsum[(size_t)NN * HH];
__device__ float g_feat[(size_t)NN * HH * 3];

// ---------------- helpers ----------------
__device__ __forceinline__ uint32_t smem_u32(const void* p) {
    uint32_t a;
    asm("{ .reg .u64 t; cvta.to.shared.u64 t, %1; cvt.u32.u64 %0, t; }" : "=r"(a) : "l"(p));
    return a;
}
__device__ __forceinline__ float gelu_tanh(float v) {
    float u = 0.7978845608028654f * (v + 0.044715f * v * v * v);
    return 0.5f * v * (1.0f + tanhf(u));
}
__device__ __forceinline__ void ldsm_x4(uint32_t& r0, uint32_t& r1, uint32_t& r2, uint32_t& r3,
                                        uint32_t addr) {
    asm volatile("ldmatrix.sync.aligned.m8n8.x4.shared.b16 {%0,%1,%2,%3}, [%4];"
                 : "=r"(r0), "=r"(r1), "=r"(r2), "=r"(r3) : "r"(addr));
}
__device__ __forceinline__ void mma16816(float* c, const uint32_t* a, const uint32_t* b) {
    asm volatile("mma.sync.aligned.m16n8k16.row.col.f32.f16.f16.f32 "
                 "{%0,%1,%2,%3},{%4,%5,%6,%7},{%8,%9},{%0,%1,%2,%3};"
                 : "+f"(c[0]), "+f"(c[1]), "+f"(c[2]), "+f"(c[3])
                 : "r"(a[0]), "r"(a[1]), "r"(a[2]), "r"(a[3]), "r"(b[0]), "r"(b[1]));
}
__device__ __forceinline__ void cp16(uint32_t dst, const void* src) {
    asm volatile("cp.async.cg.shared.global [%0], [%1], 16;" :: "r"(dst), "l"(src));
}
#define CP_COMMIT() asm volatile("cp.async.commit_group;" ::: "memory")
#define CP_WAIT1()  asm volatile("cp.async.wait_group 1;" ::: "memory")
#define CP_WAIT0()  asm volatile("cp.async.wait_group 0;" ::: "memory")

// ---------------- fused prep: weight cvts + bias concat + accumulator zeroing ----
#define PR0 (DD * DD)                       // Wq
#define PR1 (PR0 + DD * DD)                 // Wk
#define PR2 (PR1 + HID * MLPIN_P)           // W_in padded
#define PR3 (PR2 + DD * HID)                // W_out
#define PR4 (PR3 + 2 * DD)                  // bias cat
#define PR5 (PR4 + NN * HH)                 // den zero
#define PR6 (PR5 + NN * HH)                 // rowsum zero
#define PR7 (PR6 + NN * HH * 3)             // feat zero
__global__ void k_prep(const float* __restrict__ Wq, const float* __restrict__ Wk,
                       const float* __restrict__ W_in, const float* __restrict__ W_out,
                       const float* __restrict__ bq, const float* __restrict__ bk) {
    int t = blockIdx.x * blockDim.x + threadIdx.x;
    if (t < PR0) {
        g_wqkh[t] = __float2half(Wq[t]);
    } else if (t < PR1) {
        g_wqkh[t] = __float2half(Wk[t - PR0]);
    } else if (t < PR2) {
        int i = t - PR1;
        int r = i / MLPIN_P, c = i % MLPIN_P;
        g_winh[i] = (c < MLPIN) ? __float2half(W_in[(size_t)r * MLPIN + c]) : __half(0.0f);
    } else if (t < PR3) {
        int i = t - PR2;
        g_wouth[i] = __float2half(W_out[i]);
    } else if (t < PR4) {
        int i = t - PR3;
        g_bqk[i] = (i < DD) ? bq[i] : bk[i - DD];
    } else if (t < PR5) {
        g_den[t - PR4] = 0.0f;
    } else if (t < PR6) {
        g_rowsum[t - PR5] = 0.0f;
    } else if (t < PR7) {
        g_feat[t - PR6] = 0.0f;
    }
}

// ---------------- att_bias transpose [H,E] -> [E,H] ----------------
__global__ void k_tr_bias(const float* __restrict__ ab) {
    __shared__ float tile[HH][33];
    int e0 = blockIdx.x * 32;
    int t = threadIdx.x;
    int h = t >> 5, i = t & 31;
    tile[h][i] = ab[(size_t)h * EE + e0 + i];
    __syncthreads();
    int e = t >> 3, hh = t & 7;
    g_biasT[(size_t)(e0 + e) * HH + hh] = tile[hh][e];
}

// ---------------- fused double layernorm -> fp16 outputs ----------------
__global__ void k_ln(const float* __restrict__ x,
                     const float* __restrict__ ga, const float* __restrict__ ba,
                     const float* __restrict__ gm, const float* __restrict__ bm) {
    int n = blockIdx.x;
    int t = threadIdx.x;
    const float* xr = x + (size_t)n * DD;
    float v[4];
    float s = 0.0f, s2 = 0.0f;
#pragma unroll
    for (int i = 0; i < 4; i++) {
        v[i] = xr[t + 128 * i];
        s += v[i];
        s2 += v[i] * v[i];
    }
    __shared__ float shs[4], shs2[4];
#pragma unroll
    for (int o = 16; o > 0; o >>= 1) {
        s  += __shfl_xor_sync(0xffffffffu, s, o);
        s2 += __shfl_xor_sync(0xffffffffu, s2, o);
    }
    int w = t >> 5;
    if ((t & 31) == 0) { shs[w] = s; shs2[w] = s2; }
    __syncthreads();
    s  = shs[0] + shs[1] + shs[2] + shs[3];
    s2 = shs2[0] + shs2[1] + shs2[2] + shs2[3];
    float mu = s * (1.0f / DD);
    float var = s2 * (1.0f / DD) - mu * mu;
    float rstd = rsqrtf(var + 1e-5f);
#pragma unroll
    for (int i = 0; i < 4; i++) {
        int c = t + 128 * i;
        float zz = (v[i] - mu) * rstd;
        g_zh[(size_t)n * DD + c]          = __float2half(zz * ga[c] + ba[c]);
        g_mlpinh[(size_t)n * MLPIN_P + c] = __float2half(zz * gm[c] + bm[c]);
    }
}

// ---------------- HMMA GEMM (R4-proven config) ----------------
#define BM 128
#define LDT 40

template <int ACT, int RESID, int OUT16>
__global__ void __launch_bounds__(256, 2) hmma_gemm(
    const __half* __restrict__ A, const __half* __restrict__ Bw,
    const float* __restrict__ bias, const float* __restrict__ resid,
    float* __restrict__ Cf, __half* __restrict__ Ch, int K, int Nc) {
    __shared__ __half As[2][BM * LDT];
    __shared__ __half Bs[2][BM * LDT];
    const int t = threadIdx.x;
    const int lane = t & 31;
    const int w = t >> 5;
    const int wm = w >> 2;   // 0..1
    const int wn = w & 3;    // 0..3
    const __half* Ag = A  + (size_t)(blockIdx.y * 128) * K;
    const __half* Bg = Bw + (size_t)(blockIdx.x * 128) * K;
    const uint32_t sA = smem_u32(As);
    const uint32_t sB = smem_u32(Bs);

    float acc[4][4][4];
#pragma unroll
    for (int i = 0; i < 4; i++)
#pragma unroll
        for (int j = 0; j < 4; j++)
#pragma unroll
            for (int q = 0; q < 4; q++) acc[i][j][q] = 0.0f;

    const int nch = K >> 5;

#define LOAD_CHUNK(c, buf) do {                                                    \
        int _k0 = (c) << 5;                                                        \
        _Pragma("unroll")                                                          \
        for (int _s = 0; _s < 2; _s++) {                                           \
            int _seg = t + _s * 256;                                               \
            int _row = _seg >> 2, _sc = _seg & 3;                                  \
            uint32_t _off = (uint32_t)((buf) * BM * LDT + _row * LDT + _sc * 8) * 2;\
            cp16(sA + _off, Ag + (size_t)_row * K + _k0 + _sc * 8);                \
            cp16(sB + _off, Bg + (size_t)_row * K + _k0 + _sc * 8);                \
        }                                                                          \
        CP_COMMIT();                                                               \
    } while (0)

    LOAD_CHUNK(0, 0);
    for (int c = 0; c < nch; c++) {
        if (c + 1 < nch) { LOAD_CHUNK(c + 1, (c + 1) & 1); CP_WAIT1(); }
        else             { CP_WAIT0(); }
        __syncthreads();
        const int buf = c & 1;
        const uint32_t baseA = sA + (uint32_t)(buf * BM * LDT) * 2;
        const uint32_t baseB = sB + (uint32_t)(buf * BM * LDT) * 2;
#pragma unroll
        for (int ks = 0; ks < 2; ks++) {
            uint32_t a[4][4];
#pragma unroll
            for (int mf = 0; mf < 4; mf++) {
                int row = wm * 64 + mf * 16 + (lane & 15);
                int col = ks * 16 + (lane >> 4) * 8;
                ldsm_x4(a[mf][0], a[mf][1], a[mf][2], a[mf][3],
                        baseA + (uint32_t)(row * LDT + col) * 2);
            }
            uint32_t b[2][4];
#pragma unroll
            for (int nb = 0; nb < 2; nb++) {
                int row = wn * 32 + nb * 16 + (lane & 7) + ((lane >> 4) & 1) * 8;
                int col = ks * 16 + ((lane >> 3) & 1) * 8;
                ldsm_x4(b[nb][0], b[nb][1], b[nb][2], b[nb][3],
                        baseB + (uint32_t)(row * LDT + col) * 2);
            }
#pragma unroll
            for (int mf = 0; mf < 4; mf++)
#pragma unroll
                for (int nf = 0; nf < 4; nf++)
                    mma16816(acc[mf][nf], a[mf], &b[nf >> 1][(nf & 1) * 2]);
        }
        __syncthreads();
    }

    const int rBase = blockIdx.y * 128 + wm * 64 + (lane >> 2);
    const int cBase = blockIdx.x * 128 + wn * 32 + (lane & 3) * 2;
#pragma unroll
    for (int mf = 0; mf < 4; mf++) {
#pragma unroll
        for (int nf = 0; nf < 4; nf++) {
            const float* cc = acc[mf][nf];
            int col = cBase + nf * 8;
            float b0 = bias[col], b1 = bias[col + 1];
#pragma unroll
            for (int hf = 0; hf < 2; hf++) {
                int row = rBase + mf * 16 + hf * 8;
                float v0 = cc[hf * 2 + 0] + b0;
                float v1 = cc[hf * 2 + 1] + b1;
                if (ACT) { v0 = gelu_tanh(v0); v1 = gelu_tanh(v1); }
                if (RESID) {
                    const float2 r2 = *(const float2*)(resid + (size_t)row * Nc + col);
                    v0 += r2.x; v1 += r2.y;
                }
                if (OUT16) {
                    *(__half2*)(Ch + (size_t)row * Nc + col) = __floats2half2_rn(v0, v1);
                } else {
                    *(float2*)(Cf + (size_t)row * Nc + col) = make_float2(v0, v1);
                }
            }
        }
    }
#undef LOAD_CHUNK
}

// ---------------- fused edge pass (R7-proven): warp per edge, no segment max ----
__global__ void k_edge_fused(const int* __restrict__ row_index,
                             const int* __restrict__ src_index,
                             const int* __restrict__ org_to_src,
                             const float* __restrict__ dist,
                             const float* __restrict__ src_pos) {
    int e = blockIdx.x * 8 + (threadIdx.x >> 5);
    if (e >= EE) return;
    int lane = threadIdx.x & 31;
    int row = row_index[e];
    int si  = src_index[e];
    int src = org_to_src[si];
    const __half2* qr = (const __half2*)(g_qkh + (size_t)row * (2 * DD));
    const __half2* kr = (const __half2*)(g_qkh + (size_t)src * (2 * DD) + DD);
    float myLogit = 0.0f;
#pragma unroll
    for (int h = 0; h < HH; h++) {
        float2 q2 = __half22float2(qr[h * 32 + lane]);
        float2 k2 = __half22float2(kr[h * 32 + lane]);
        float s = q2.x * k2.x + q2.y * k2.y;
#pragma unroll
        for (int o = 16; o > 0; o >>= 1) s += __shfl_xor_sync(0xffffffffu, s, o);
        if (lane == h) myLogit = s;
    }
    if (lane < HH) {
        float l = myLogit * 0.125f + g_biasT[(size_t)e * HH + lane];
        float p = __expf(l);
        float d = dist[e];
        float w = (d == 0.0f) ? 0.0f : p / d;
        float sx = src_pos[3 * si + 0];
        float sy = src_pos[3 * si + 1];
        float sz = src_pos[3 * si + 2];
        atomicAdd(&g_den[row * HH + lane], p);
        atomicAdd(&g_rowsum[row * HH + lane], w);
        float* f = &g_feat[(size_t)row * 24 + lane * 3];
        atomicAdd(f + 0, w * sx);
        atomicAdd(f + 1, w * sy);
        atomicAdd(f + 2, w * sz);
    }
}

// ---------------- node finalize: feat -> mlp_in tail (fp16) + zero pad ----------------
__global__ void k_node_fin(const float* __restrict__ pos) {
    int t = blockIdx.x * blockDim.x + threadIdx.x;
    if (t >= NN * 32) return;
    int n = t >> 5;
    int r = t & 31;
    if (r < 24) {
        int h = r / 3;
        int j = r % 3;
        float dn = g_den[n * HH + h];
        float inv = (dn != 0.0f) ? (1.0f / dn) : 0.0f;
        float f = g_feat[n * 24 + r] * inv - g_rowsum[n * HH + h] * inv * pos[n * 3 + j];
        g_mlpinh[(size_t)n * MLPIN_P + DD + r] = __float2half(f);
    } else {
        g_mlpinh[(size_t)n * MLPIN_P + DD + r] = __half(0.0f);
    }
}

// ---------------- launch ----------------
extern "C" void kernel_launch(void* const* d_in, const int* in_sizes, int n_in,
                              void* d_out, int out_size) {
    const float* x        = (const float*)d_in[0];
    const float* Wq       = (const float*)d_in[1];
    const float* bq       = (const float*)d_in[2];
    const float* Wk       = (const float*)d_in[3];
    const float* bk       = (const float*)d_in[4];
    const float* g_att    = (const float*)d_in[5];
    const float* b_att    = (const float*)d_in[6];
    const float* g_mlp    = (const float*)d_in[7];
    const float* b_mlp    = (const float*)d_in[8];
    const float* W_in     = (const float*)d_in[9];
    const float* b_in     = (const float*)d_in[10];
    const float* W_out    = (const float*)d_in[11];
    const float* b_out    = (const float*)d_in[12];
    const float* att_bias = (const float*)d_in[13];
    const float* dist     = (const float*)d_in[14];
    const float* pos      = (const float*)d_in[15];
    const float* src_pos  = (const float*)d_in[16];
    const int*   row_index  = (const int*)d_in[17];
    const int*   src_index  = (const int*)d_in[18];
    const int*   org_to_src = (const int*)d_in[19];
    float* out = (float*)d_out;

    __half *pzh, *pmlpinh, *phidh, *pqkh, *pwqkh, *pwinh, *pwouth;
    float* pbqk;
    cudaGetSymbolAddress((void**)&pzh, g_zh);
    cudaGetSymbolAddress((void**)&pmlpinh, g_mlpinh);
    cudaGetSymbolAddress((void**)&phidh, g_hidh);
    cudaGetSymbolAddress((void**)&pqkh, g_qkh);
    cudaGetSymbolAddress((void**)&pwqkh, g_wqkh);
    cudaGetSymbolAddress((void**)&pwinh, g_winh);
    cudaGetSymbolAddress((void**)&pwouth, g_wouth);
    cudaGetSymbolAddress((void**)&pbqk, g_bqk);

    k_prep<<<(PR7 + 255) / 256, 256>>>(Wq, Wk, W_in, W_out, bq, bk);
    k_tr_bias<<<EE / 32, 256>>>(att_bias);
    k_ln<<<NN, 128>>>(x, g_att, b_att, g_mlp, b_mlp);
    // [q|k] = z @ [Wq;Wk]^T + [bq;bk]  -> fp16 [N, 1024]
    hmma_gemm<0, 0, 1><<<dim3(2 * DD / 128, NN / 128), 256>>>(
        pzh, pwqkh, pbqk, nullptr, nullptr, pqkh, DD, 2 * DD);
    k_edge_fused<<<EE / 8, 256>>>(row_index, src_index, org_to_src, dist, src_pos);
    k_node_fin<<<(NN * 32 + 255) / 256, 256>>>(pos);
    // hid = gelu(mlpin @ W_in^T + b_in) -> fp16
    hmma_gemm<1, 0, 1><<<dim3(HID / 128, NN / 128), 256>>>(
        pmlpinh, pwinh, b_in, nullptr, nullptr, phidh, MLPIN_P, HID);
    // out = x + hid @ W_out^T + b_out -> fp32
    hmma_gemm<0, 1, 0><<<dim3(DD / 128, NN / 128), 256>>>(
        phidh, pwouth, b_out, x, out, nullptr, HID, DD);
}

// round 14
// speedup vs baseline: 1.2719x; 1.0364x over previous
#include <cuda_runtime.h>
#include <cuda_fp16.h>
#include <cstdint>

// ---------------- problem constants ----------------
#define NN   16384      // nodes
#define EE   262144     // edges
#define DD   512        // embed dim
#define HH   8          // heads
#define HID  1024       // mlp hidden
#define MLPIN 536       // D + 3*H
#define MLPIN_P 544     // padded to /32

// ---------------- device scratch (no allocations allowed) ----------------
__device__ __half g_zh[(size_t)NN * DD];          // LN(att) fp16
__device__ __half g_mlpinh[(size_t)NN * MLPIN_P]; // [z_mlp | feat | 0pad] fp16
__device__ __half g_hidh[(size_t)NN * HID];       // gelu(hidden) fp16
__device__ __half g_qkh[(size_t)NN * 2 * DD];     // [q | k] fp16 per node
__device__ __half g_wqkh[(size_t)2 * DD * DD];    // [Wq; Wk] fp16
__device__ __half g_winh[(size_t)HID * MLPIN_P];
__device__ __half g_wouth[(size_t)DD * HID];
__device__ float g_bqk[2 * DD];
__device__ float g_biasT[(size_t)EE * HH];        // att_bias transposed [E,H]
__device__ float g_den[(size_t)NN * HH];
__device__ float4 g_featw[(size_t)NN * HH];       // (fx, fy, fz, rowsum) per (row,head)

// ---------------- helpers ----------------
__device__ __forceinline__ uint32_t smem_u32(const void* p) {
    uint32_t a;
    asm("{ .reg .u64 t; cvta.to.shared.u64 t, %1; cvt.u32.u64 %0, t; }" : "=r"(a) : "l"(p));
    return a;
}
__device__ __forceinline__ float gelu_tanh(float v) {
    float u = 0.7978845608028654f * (v + 0.044715f * v * v * v);
    return 0.5f * v * (1.0f + tanhf(u));
}
__device__ __forceinline__ void ldsm_x4(uint32_t& r0, uint32_t& r1, uint32_t& r2, uint32_t& r3,
                                        uint32_t addr) {
    asm volatile("ldmatrix.sync.aligned.m8n8.x4.shared.b16 {%0,%1,%2,%3}, [%4];"
                 : "=r"(r0), "=r"(r1), "=r"(r2), "=r"(r3) : "r"(addr));
}
__device__ __forceinline__ void mma16816(float* c, const uint32_t* a, const uint32_t* b) {
    asm volatile("mma.sync.aligned.m16n8k16.row.col.f32.f16.f16.f32 "
                 "{%0,%1,%2,%3},{%4,%5,%6,%7},{%8,%9},{%0,%1,%2,%3};"
                 : "+f"(c[0]), "+f"(c[1]), "+f"(c[2]), "+f"(c[3])
                 : "r"(a[0]), "r"(a[1]), "r"(a[2]), "r"(a[3]), "r"(b[0]), "r"(b[1]));
}
__device__ __forceinline__ void cp16(uint32_t dst, const void* src) {
    asm volatile("cp.async.cg.shared.global [%0], [%1], 16;" :: "r"(dst), "l"(src));
}
#define CP_COMMIT() asm volatile("cp.async.commit_group;" ::: "memory")
#define CP_WAIT1()  asm volatile("cp.async.wait_group 1;" ::: "memory")
#define CP_WAIT0()  asm volatile("cp.async.wait_group 0;" ::: "memory")

// 16-half fp32 dot of two int4-packed fragments
__device__ __forceinline__ float dot16(int4 a, int4 b) {
    const __half2* pa = (const __half2*)&a;
    const __half2* pb = (const __half2*)&b;
    float s = 0.0f;
#pragma unroll
    for (int i = 0; i < 4; i++) {
        float2 fa = __half22float2(pa[i]);
        float2 fb = __half22float2(pb[i]);
        s += fa.x * fb.x + fa.y * fb.y;
    }
    return s;
}
// vectorized global reduction (PTX 8.1, sm_90+)
__device__ __forceinline__ void red_add_v4(float4* addr, float a, float b, float c, float d) {
    asm volatile("red.global.add.v4.f32 [%0], {%1, %2, %3, %4};"
                 :: "l"(addr), "f"(a), "f"(b), "f"(c), "f"(d) : "memory");
}

// ---------------- fused prep: weight cvts + bias concat + accumulator zeroing ----
#define PR0 (DD * DD)                       // Wq
#define PR1 (PR0 + DD * DD)                 // Wk
#define PR2 (PR1 + HID * MLPIN_P)           // W_in padded
#define PR3 (PR2 + DD * HID)                // W_out
#define PR4 (PR3 + 2 * DD)                  // bias cat
#define PR5 (PR4 + NN * HH)                 // den zero
#define PR6 (PR5 + NN * HH * 4)             // featw zero
__global__ void k_prep(const float* __restrict__ Wq, const float* __restrict__ Wk,
                       const float* __restrict__ W_in, const float* __restrict__ W_out,
                       const float* __restrict__ bq, const float* __restrict__ bk) {
    int t = blockIdx.x * blockDim.x + threadIdx.x;
    if (t < PR0) {
        g_wqkh[t] = __float2half(Wq[t]);
    } else if (t < PR1) {
        g_wqkh[t] = __float2half(Wk[t - PR0]);
    } else if (t < PR2) {
        int i = t - PR1;
        int r = i / MLPIN_P, c = i % MLPIN_P;
        g_winh[i] = (c < MLPIN) ? __float2half(W_in[(size_t)r * MLPIN + c]) : __half(0.0f);
    } else if (t < PR3) {
        int i = t - PR2;
        g_wouth[i] = __float2half(W_out[i]);
    } else if (t < PR4) {
        int i = t - PR3;
        g_bqk[i] = (i < DD) ? bq[i] : bk[i - DD];
    } else if (t < PR5) {
        g_den[t - PR4] = 0.0f;
    } else if (t < PR6) {
        ((float*)g_featw)[t - PR5] = 0.0f;
    }
}

// ---------------- att_bias transpose [H,E] -> [E,H] ----------------
__global__ void k_tr_bias(const float* __restrict__ ab) {
    __shared__ float tile[HH][33];
    int e0 = blockIdx.x * 32;
    int t = threadIdx.x;
    int h = t >> 5, i = t & 31;
    tile[h][i] = ab[(size_t)h * EE + e0 + i];
    __syncthreads();
    int e = t >> 3, hh = t & 7;
    g_biasT[(size_t)(e0 + e) * HH + hh] = tile[hh][e];
}

// ---------------- fused double layernorm -> fp16 outputs ----------------
__global__ void k_ln(const float* __restrict__ x,
                     const float* __restrict__ ga, const float* __restrict__ ba,
                     const float* __restrict__ gm, const float* __restrict__ bm) {
    int n = blockIdx.x;
    int t = threadIdx.x;
    const float* xr = x + (size_t)n * DD;
    float v[4];
    float s = 0.0f, s2 = 0.0f;
#pragma unroll
    for (int i = 0; i < 4; i++) {
        v[i] = xr[t + 128 * i];
        s += v[i];
        s2 += v[i] * v[i];
    }
    __shared__ float shs[4], shs2[4];
#pragma unroll
    for (int o = 16; o > 0; o >>= 1) {
        s  += __shfl_xor_sync(0xffffffffu, s, o);
        s2 += __shfl_xor_sync(0xffffffffu, s2, o);
    }
    int w = t >> 5;
    if ((t & 31) == 0) { shs[w] = s; shs2[w] = s2; }
    __syncthreads();
    s  = shs[0] + shs[1] + shs[2] + shs[3];
    s2 = shs2[0] + shs2[1] + shs2[2] + shs2[3];
    float mu = s * (1.0f / DD);
    float var = s2 * (1.0f / DD) - mu * mu;
    float rstd = rsqrtf(var + 1e-5f);
#pragma unroll
    for (int i = 0; i < 4; i++) {
        int c = t + 128 * i;
        float zz = (v[i] - mu) * rstd;
        g_zh[(size_t)n * DD + c]          = __float2half(zz * ga[c] + ba[c]);
        g_mlpinh[(size_t)n * MLPIN_P + c] = __float2half(zz * gm[c] + bm[c]);
    }
}

// ---------------- HMMA GEMM (R4-proven config; measured 94% of mma.sync ceiling) ----
#define BM 128
#define LDT 40

template <int ACT, int RESID, int OUT16>
__global__ void __launch_bounds__(256, 2) hmma_gemm(
    const __half* __restrict__ A, const __half* __restrict__ Bw,
    const float* __restrict__ bias, const float* __restrict__ resid,
    float* __restrict__ Cf, __half* __restrict__ Ch, int K, int Nc) {
    __shared__ __half As[2][BM * LDT];
    __shared__ __half Bs[2][BM * LDT];
    const int t = threadIdx.x;
    const int lane = t & 31;
    const int w = t >> 5;
    const int wm = w >> 2;   // 0..1
    const int wn = w & 3;    // 0..3
    const __half* Ag = A  + (size_t)(blockIdx.y * 128) * K;
    const __half* Bg = Bw + (size_t)(blockIdx.x * 128) * K;
    const uint32_t sA = smem_u32(As);
    const uint32_t sB = smem_u32(Bs);

    float acc[4][4][4];
#pragma unroll
    for (int i = 0; i < 4; i++)
#pragma unroll
        for (int j = 0; j < 4; j++)
#pragma unroll
            for (int q = 0; q < 4; q++) acc[i][j][q] = 0.0f;

    const int nch = K >> 5;

#define LOAD_CHUNK(c, buf) do {                                                    \
        int _k0 = (c) << 5;                                                        \
        _Pragma("unroll")                                                          \
        for (int _s = 0; _s < 2; _s++) {                                           \
            int _seg = t + _s * 256;                                               \
            int _row = _seg >> 2, _sc = _seg & 3;                                  \
            uint32_t _off = (uint32_t)((buf) * BM * LDT + _row * LDT + _sc * 8) * 2;\
            cp16(sA + _off, Ag + (size_t)_row * K + _k0 + _sc * 8);                \
            cp16(sB + _off, Bg + (size_t)_row * K + _k0 + _sc * 8);                \
        }                                                                          \
        CP_COMMIT();                                                               \
    } while (0)

    LOAD_CHUNK(0, 0);
    for (int c = 0; c < nch; c++) {
        if (c + 1 < nch) { LOAD_CHUNK(c + 1, (c + 1) & 1); CP_WAIT1(); }
        else             { CP_WAIT0(); }
        __syncthreads();
        const int buf = c & 1;
        const uint32_t baseA = sA + (uint32_t)(buf * BM * LDT) * 2;
        const uint32_t baseB = sB + (uint32_t)(buf * BM * LDT) * 2;
#pragma unroll
        for (int ks = 0; ks < 2; ks++) {
            uint32_t a[4][4];
#pragma unroll
            for (int mf = 0; mf < 4; mf++) {
                int row = wm * 64 + mf * 16 + (lane & 15);
                int col = ks * 16 + (lane >> 4) * 8;
                ldsm_x4(a[mf][0], a[mf][1], a[mf][2], a[mf][3],
                        baseA + (uint32_t)(row * LDT + col) * 2);
            }
            uint32_t b[2][4];
#pragma unroll
            for (int nb = 0; nb < 2; nb++) {
                int row = wn * 32 + nb * 16 + (lane & 7) + ((lane >> 4) & 1) * 8;
                int col = ks * 16 + ((lane >> 3) & 1) * 8;
                ldsm_x4(b[nb][0], b[nb][1], b[nb][2], b[nb][3],
                        baseB + (uint32_t)(row * LDT + col) * 2);
            }
#pragma unroll
            for (int mf = 0; mf < 4; mf++)
#pragma unroll
                for (int nf = 0; nf < 4; nf++)
                    mma16816(acc[mf][nf], a[mf], &b[nf >> 1][(nf & 1) * 2]);
        }
        __syncthreads();
    }

    const int rBase = blockIdx.y * 128 + wm * 64 + (lane >> 2);
    const int cBase = blockIdx.x * 128 + wn * 32 + (lane & 3) * 2;
#pragma unroll
    for (int mf = 0; mf < 4; mf++) {
#pragma unroll
        for (int nf = 0; nf < 4; nf++) {
            const float* cc = acc[mf][nf];
            int col = cBase + nf * 8;
            float b0 = bias[col], b1 = bias[col + 1];
#pragma unroll
            for (int hf = 0; hf < 2; hf++) {
                int row = rBase + mf * 16 + hf * 8;
                float v0 = cc[hf * 2 + 0] + b0;
                float v1 = cc[hf * 2 + 1] + b1;
                if (ACT) { v0 = gelu_tanh(v0); v1 = gelu_tanh(v1); }
                if (RESID) {
                    const float2 r2 = *(const float2*)(resid + (size_t)row * Nc + col);
                    v0 += r2.x; v1 += r2.y;
                }
                if (OUT16) {
                    *(__half2*)(Ch + (size_t)row * Nc + col) = __floats2half2_rn(v0, v1);
                } else {
                    *(float2*)(Cf + (size_t)row * Nc + col) = make_float2(v0, v1);
                }
            }
        }
    }
#undef LOAD_CHUNK
}

// ---------------- edge pass v2: warp per edge, wide loads + 8-lane group reduce ----
// q/k rows loaded as 4x int4 per lane (16B); lane L's first fragment belongs to
// head L>>3 (dims 8*(L&7)..+8), second fragment to head 4+(L>>3). All 8 heads
// reduce simultaneously in 3 butterfly rounds over 8-lane groups.
// Scatter: one red.v4 (fx,fy,fz,w) + one scalar red (den) per (edge,head).
__global__ void k_edge_fused(const int* __restrict__ row_index,
                             const int* __restrict__ src_index,
                             const int* __restrict__ org_to_src,
                             const float* __restrict__ dist,
                             const float* __restrict__ src_pos) {
    int e = blockIdx.x * 8 + (threadIdx.x >> 5);
    int lane = threadIdx.x & 31;
    int row = row_index[e];
    int si  = src_index[e];
    int src = org_to_src[si];
    const int4* qr = (const int4*)(g_qkh + (size_t)row * (2 * DD));
    const int4* kr = (const int4*)(g_qkh + (size_t)src * (2 * DD) + DD);
    int4 q1 = qr[lane], q2 = qr[lane + 32];
    int4 k1 = kr[lane], k2 = kr[lane + 32];
    float s1 = dot16(q1, k1);   // head lane>>3
    float s2 = dot16(q2, k2);   // head 4 + (lane>>3)
#pragma unroll
    for (int o = 4; o > 0; o >>= 1) {
        s1 += __shfl_xor_sync(0xffffffffu, s1, o);
        s2 += __shfl_xor_sync(0xffffffffu, s2, o);
    }
    // head h logit lives at lane 8*(h&3) in s1 (h<4) / s2 (h>=4)
    float t1 = __shfl_sync(0xffffffffu, s1, (lane & 3) * 8);
    float t2 = __shfl_sync(0xffffffffu, s2, (lane & 3) * 8);
    if (lane < HH) {
        float cap = (lane < 4) ? t1 : t2;
        float l = cap * 0.125f + g_biasT[(size_t)e * HH + lane];
        float p = __expf(l);
        float d = dist[e];
        float w = (d == 0.0f) ? 0.0f : p / d;
        float sx = src_pos[3 * si + 0];
        float sy = src_pos[3 * si + 1];
        float sz = src_pos[3 * si + 2];
        red_add_v4(&g_featw[(size_t)row * HH + lane], w * sx, w * sy, w * sz, w);
        atomicAdd(&g_den[row * HH + lane], p);
    }
}

// ---------------- node finalize: featw -> mlp_in tail (fp16) + zero pad ----------------
__global__ void k_node_fin(const float* __restrict__ pos) {
    int t = blockIdx.x * blockDim.x + threadIdx.x;
    if (t >= NN * 32) return;
    int n = t >> 5;
    int r = t & 31;
    if (r < 24) {
        int h = r / 3;
        int j = r % 3;
        float4 fw = g_featw[n * HH + h];
        float dn = g_den[n * HH + h];
        float inv = (dn != 0.0f) ? (1.0f / dn) : 0.0f;
        float comp = (j == 0) ? fw.x : ((j == 1) ? fw.y : fw.z);
        float f = comp * inv - fw.w * inv * pos[n * 3 + j];
        g_mlpinh[(size_t)n * MLPIN_P + DD + r] = __float2half(f);
    } else {
        g_mlpinh[(size_t)n * MLPIN_P + DD + r] = __half(0.0f);
    }
}

// ---------------- launch ----------------
extern "C" void kernel_launch(void* const* d_in, const int* in_sizes, int n_in,
                              void* d_out, int out_size) {
    const float* x        = (const float*)d_in[0];
    const float* Wq       = (const float*)d_in[1];
    const float* bq       = (const float*)d_in[2];
    const float* Wk       = (const float*)d_in[3];
    const float* bk       = (const float*)d_in[4];
    const float* g_att    = (const float*)d_in[5];
    const float* b_att    = (const float*)d_in[6];
    const float* g_mlp    = (const float*)d_in[7];
    const float* b_mlp    = (const float*)d_in[8];
    const float* W_in     = (const float*)d_in[9];
    const float* b_in     = (const float*)d_in[10];
    const float* W_out    = (const float*)d_in[11];
    const float* b_out    = (const float*)d_in[12];
    const float* att_bias = (const float*)d_in[13];
    const float* dist     = (const float*)d_in[14];
    const float* pos      = (const float*)d_in[15];
    const float* src_pos  = (const float*)d_in[16];
    const int*   row_index  = (const int*)d_in[17];
    const int*   src_index  = (const int*)d_in[18];
    const int*   org_to_src = (const int*)d_in[19];
    float* out = (float*)d_out;

    __half *pzh, *pmlpinh, *phidh, *pqkh, *pwqkh, *pwinh, *pwouth;
    float* pbqk;
    cudaGetSymbolAddress((void**)&pzh, g_zh);
    cudaGetSymbolAddress((void**)&pmlpinh, g_mlpinh);
    cudaGetSymbolAddress((void**)&phidh, g_hidh);
    cudaGetSymbolAddress((void**)&pqkh, g_qkh);
    cudaGetSymbolAddress((void**)&pwqkh, g_wqkh);
    cudaGetSymbolAddress((void**)&pwinh, g_winh);
    cudaGetSymbolAddress((void**)&pwouth, g_wouth);
    cudaGetSymbolAddress((void**)&pbqk, g_bqk);

    k_prep<<<(PR6 + 255) / 256, 256>>>(Wq, Wk, W_in, W_out, bq, bk);
    k_tr_bias<<<EE / 32, 256>>>(att_bias);
    k_ln<<<NN, 128>>>(x, g_att, b_att, g_mlp, b_mlp);
    // [q|k] = z @ [Wq;Wk]^T + [bq;bk]  -> fp16 [N, 1024]
    hmma_gemm<0, 0, 1><<<dim3(2 * DD / 128, NN / 128), 256>>>(
        pzh, pwqkh, pbqk, nullptr, nullptr, pqkh, DD, 2 * DD);
    k_edge_fused<<<EE / 8, 256>>>(row_index, src_index, org_to_src, dist, src_pos);
    k_node_fin<<<(NN * 32 + 255) / 256, 256>>>(pos);
    // hid = gelu(mlpin @ W_in^T + b_in) -> fp16
    hmma_gemm<1, 0, 1><<<dim3(HID / 128, NN / 128), 256>>>(
        pmlpinh, pwinh, b_in, nullptr, nullptr, phidh, MLPIN_P, HID);
    // out = x + hid @ W_out^T + b_out -> fp32
    hmma_gemm<0, 1, 0><<<dim3(DD / 128, NN / 128), 256>>>(
        phidh, pwouth, b_out, x, out, nullptr, HID, DD);
}

// round 16
// speedup vs baseline: 1.3086x; 1.0288x over previous
#include <cuda_runtime.h>
#include <cuda_fp16.h>
#include <cstdint>

// ---------------- problem constants ----------------
#define NN   16384      // nodes
#define EE   262144     // edges
#define DD   512        // embed dim
#define HH   8          // heads
#define HID  1024       // mlp hidden
#define MLPIN 536       // D + 3*H
#define MLPIN_P 544     // padded to /32

// ---------------- device scratch (no allocations allowed) ----------------
__device__ __half g_zh[(size_t)NN * DD];          // LN(att) fp16
__device__ __half g_mlpinh[(size_t)NN * MLPIN_P]; // [z_mlp | feat | 0pad] fp16
__device__ __half g_hidh[(size_t)NN * HID];       // gelu(hidden) fp16
__device__ __half g_qkh[(size_t)NN * 2 * DD];     // [q | k] fp16 per node
__device__ __half g_wqkh[(size_t)2 * DD * DD];    // [Wq; Wk] fp16
__device__ __half g_winh[(size_t)HID * MLPIN_P];
__device__ __half g_wouth[(size_t)DD * HID];
__device__ float g_bqk[2 * DD];
__device__ float g_biasT[(size_t)EE * HH];        // att_bias transposed [E,H]
__device__ float g_den[(size_t)NN * HH];
__device__ float4 g_featw[(size_t)NN * HH];       // (fx, fy, fz, rowsum) per (row,head)

// ---------------- helpers ----------------
__device__ __forceinline__ uint32_t smem_u32(const void* p) {
    uint32_t a;
    asm("{ .reg .u64 t; cvta.to.shared.u64 t, %1; cvt.u32.u64 %0, t; }" : "=r"(a) : "l"(p));
    return a;
}
__device__ __forceinline__ float gelu_tanh(float v) {
    float u = 0.7978845608028654f * (v + 0.044715f * v * v * v);
    return 0.5f * v * (1.0f + tanhf(u));
}
__device__ __forceinline__ void ldsm_x4(uint32_t& r0, uint32_t& r1, uint32_t& r2, uint32_t& r3,
                                        uint32_t addr) {
    asm volatile("ldmatrix.sync.aligned.m8n8.x4.shared.b16 {%0,%1,%2,%3}, [%4];"
                 : "=r"(r0), "=r"(r1), "=r"(r2), "=r"(r3) : "r"(addr));
}
__device__ __forceinline__ void mma16816(float* c, const uint32_t* a, const uint32_t* b) {
    asm volatile("mma.sync.aligned.m16n8k16.row.col.f32.f16.f16.f32 "
                 "{%0,%1,%2,%3},{%4,%5,%6,%7},{%8,%9},{%0,%1,%2,%3};"
                 : "+f"(c[0]), "+f"(c[1]), "+f"(c[2]), "+f"(c[3])
                 : "r"(a[0]), "r"(a[1]), "r"(a[2]), "r"(a[3]), "r"(b[0]), "r"(b[1]));
}
__device__ __forceinline__ void cp16(uint32_t dst, const void* src) {
    asm volatile("cp.async.cg.shared.global [%0], [%1], 16;" :: "r"(dst), "l"(src));
}
#define CP_COMMIT() asm volatile("cp.async.commit_group;" ::: "memory")
#define CP_WAIT1()  asm volatile("cp.async.wait_group 1;" ::: "memory")
#define CP_WAIT0()  asm volatile("cp.async.wait_group 0;" ::: "memory")

// 16-half fp32 dot of two int4-packed fragments
__device__ __forceinline__ float dot16(int4 a, int4 b) {
    const __half2* pa = (const __half2*)&a;
    const __half2* pb = (const __half2*)&b;
    float s = 0.0f;
#pragma unroll
    for (int i = 0; i < 4; i++) {
        float2 fa = __half22float2(pa[i]);
        float2 fb = __half22float2(pb[i]);
        s += fa.x * fb.x + fa.y * fb.y;
    }
    return s;
}
// vectorized global reduction (PTX 8.1, sm_90+)
__device__ __forceinline__ void red_add_v4(float4* addr, float a, float b, float c, float d) {
    asm volatile("red.global.add.v4.f32 [%0], {%1, %2, %3, %4};"
                 :: "l"(addr), "f"(a), "f"(b), "f"(c), "f"(d) : "memory");
}

// ---------------- fused prep: weight cvts + bias concat + accumulator zeroing ----
#define PR0 (DD * DD)                       // Wq
#define PR1 (PR0 + DD * DD)                 // Wk
#define PR2 (PR1 + HID * MLPIN_P)           // W_in padded
#define PR3 (PR2 + DD * HID)                // W_out
#define PR4 (PR3 + 2 * DD)                  // bias cat
#define PR5 (PR4 + NN * HH)                 // den zero
#define PR6 (PR5 + NN * HH * 4)             // featw zero
__global__ void k_prep(const float* __restrict__ Wq, const float* __restrict__ Wk,
                       const float* __restrict__ W_in, const float* __restrict__ W_out,
                       const float* __restrict__ bq, const float* __restrict__ bk) {
    int t = blockIdx.x * blockDim.x + threadIdx.x;
    if (t < PR0) {
        g_wqkh[t] = __float2half(Wq[t]);
    } else if (t < PR1) {
        g_wqkh[t] = __float2half(Wk[t - PR0]);
    } else if (t < PR2) {
        int i = t - PR1;
        int r = i / MLPIN_P, c = i % MLPIN_P;
        g_winh[i] = (c < MLPIN) ? __float2half(W_in[(size_t)r * MLPIN + c]) : __half(0.0f);
    } else if (t < PR3) {
        int i = t - PR2;
        g_wouth[i] = __float2half(W_out[i]);
    } else if (t < PR4) {
        int i = t - PR3;
        g_bqk[i] = (i < DD) ? bq[i] : bk[i - DD];
    } else if (t < PR5) {
        g_den[t - PR4] = 0.0f;
    } else if (t < PR6) {
        ((float*)g_featw)[t - PR5] = 0.0f;
    }
}

// ---------------- att_bias transpose [H,E] -> [E,H] ----------------
__global__ void k_tr_bias(const float* __restrict__ ab) {
    __shared__ float tile[HH][33];
    int e0 = blockIdx.x * 32;
    int t = threadIdx.x;
    int h = t >> 5, i = t & 31;
    tile[h][i] = ab[(size_t)h * EE + e0 + i];
    __syncthreads();
    int e = t >> 3, hh = t & 7;
    g_biasT[(size_t)(e0 + e) * HH + hh] = tile[hh][e];
}

// ---------------- fused double layernorm -> fp16 outputs ----------------
__global__ void k_ln(const float* __restrict__ x,
                     const float* __restrict__ ga, const float* __restrict__ ba,
                     const float* __restrict__ gm, const float* __restrict__ bm) {
    int n = blockIdx.x;
    int t = threadIdx.x;
    const float* xr = x + (size_t)n * DD;
    float v[4];
    float s = 0.0f, s2 = 0.0f;
#pragma unroll
    for (int i = 0; i < 4; i++) {
        v[i] = xr[t + 128 * i];
        s += v[i];
        s2 += v[i] * v[i];
    }
    __shared__ float shs[4], shs2[4];
#pragma unroll
    for (int o = 16; o > 0; o >>= 1) {
        s  += __shfl_xor_sync(0xffffffffu, s, o);
        s2 += __shfl_xor_sync(0xffffffffu, s2, o);
    }
    int w = t >> 5;
    if ((t & 31) == 0) { shs[w] = s; shs2[w] = s2; }
    __syncthreads();
    s  = shs[0] + shs[1] + shs[2] + shs[3];
    s2 = shs2[0] + shs2[1] + shs2[2] + shs2[3];
    float mu = s * (1.0f / DD);
    float var = s2 * (1.0f / DD) - mu * mu;
    float rstd = rsqrtf(var + 1e-5f);
#pragma unroll
    for (int i = 0; i < 4; i++) {
        int c = t + 128 * i;
        float zz = (v[i] - mu) * rstd;
        g_zh[(size_t)n * DD + c]          = __float2half(zz * ga[c] + ba[c]);
        g_mlpinh[(size_t)n * MLPIN_P + c] = __float2half(zz * gm[c] + bm[c]);
    }
}

// ---------------- HMMA GEMM (R4-proven config; measured 94% of mma.sync ceiling) ----
#define BM 128
#define LDT 40

template <int ACT, int RESID, int OUT16>
__global__ void __launch_bounds__(256, 2) hmma_gemm(
    const __half* __restrict__ A, const __half* __restrict__ Bw,
    const float* __restrict__ bias, const float* __restrict__ resid,
    float* __restrict__ Cf, __half* __restrict__ Ch, int K, int Nc) {
    __shared__ __half As[2][BM * LDT];
    __shared__ __half Bs[2][BM * LDT];
    const int t = threadIdx.x;
    const int lane = t & 31;
    const int w = t >> 5;
    const int wm = w >> 2;   // 0..1
    const int wn = w & 3;    // 0..3
    const __half* Ag = A  + (size_t)(blockIdx.y * 128) * K;
    const __half* Bg = Bw + (size_t)(blockIdx.x * 128) * K;
    const uint32_t sA = smem_u32(As);
    const uint32_t sB = smem_u32(Bs);

    float acc[4][4][4];
#pragma unroll
    for (int i = 0; i < 4; i++)
#pragma unroll
        for (int j = 0; j < 4; j++)
#pragma unroll
            for (int q = 0; q < 4; q++) acc[i][j][q] = 0.0f;

    const int nch = K >> 5;

#define LOAD_CHUNK(c, buf) do {                                                    \
        int _k0 = (c) << 5;                                                        \
        _Pragma("unroll")                                                          \
        for (int _s = 0; _s < 2; _s++) {                                           \
            int _seg = t + _s * 256;                                               \
            int _row = _seg >> 2, _sc = _seg & 3;                                  \
            uint32_t _off = (uint32_t)((buf) * BM * LDT + _row * LDT + _sc * 8) * 2;\
            cp16(sA + _off, Ag + (size_t)_row * K + _k0 + _sc * 8);                \
            cp16(sB + _off, Bg + (size_t)_row * K + _k0 + _sc * 8);                \
        }                                                                          \
        CP_COMMIT();                                                               \
    } while (0)

    LOAD_CHUNK(0, 0);
    for (int c = 0; c < nch; c++) {
        if (c + 1 < nch) { LOAD_CHUNK(c + 1, (c + 1) & 1); CP_WAIT1(); }
        else             { CP_WAIT0(); }
        __syncthreads();
        const int buf = c & 1;
        const uint32_t baseA = sA + (uint32_t)(buf * BM * LDT) * 2;
        const uint32_t baseB = sB + (uint32_t)(buf * BM * LDT) * 2;
#pragma unroll
        for (int ks = 0; ks < 2; ks++) {
            uint32_t a[4][4];
#pragma unroll
            for (int mf = 0; mf < 4; mf++) {
                int row = wm * 64 + mf * 16 + (lane & 15);
                int col = ks * 16 + (lane >> 4) * 8;
                ldsm_x4(a[mf][0], a[mf][1], a[mf][2], a[mf][3],
                        baseA + (uint32_t)(row * LDT + col) * 2);
            }
            uint32_t b[2][4];
#pragma unroll
            for (int nb = 0; nb < 2; nb++) {
                int row = wn * 32 + nb * 16 + (lane & 7) + ((lane >> 4) & 1) * 8;
                int col = ks * 16 + ((lane >> 3) & 1) * 8;
                ldsm_x4(b[nb][0], b[nb][1], b[nb][2], b[nb][3],
                        baseB + (uint32_t)(row * LDT + col) * 2);
            }
#pragma unroll
            for (int mf = 0; mf < 4; mf++)
#pragma unroll
                for (int nf = 0; nf < 4; nf++)
                    mma16816(acc[mf][nf], a[mf], &b[nf >> 1][(nf & 1) * 2]);
        }
        __syncthreads();
    }

    const int rBase = blockIdx.y * 128 + wm * 64 + (lane >> 2);
    const int cBase = blockIdx.x * 128 + wn * 32 + (lane & 3) * 2;
#pragma unroll
    for (int mf = 0; mf < 4; mf++) {
#pragma unroll
        for (int nf = 0; nf < 4; nf++) {
            const float* cc = acc[mf][nf];
            int col = cBase + nf * 8;
            float b0 = bias[col], b1 = bias[col + 1];
#pragma unroll
            for (int hf = 0; hf < 2; hf++) {
                int row = rBase + mf * 16 + hf * 8;
                float v0 = cc[hf * 2 + 0] + b0;
                float v1 = cc[hf * 2 + 1] + b1;
                if (ACT) { v0 = gelu_tanh(v0); v1 = gelu_tanh(v1); }
                if (RESID) {
                    const float2 r2 = *(const float2*)(resid + (size_t)row * Nc + col);
                    v0 += r2.x; v1 += r2.y;
                }
                if (OUT16) {
                    *(__half2*)(Ch + (size_t)row * Nc + col) = __floats2half2_rn(v0, v1);
                } else {
                    *(float2*)(Cf + (size_t)row * Nc + col) = make_float2(v0, v1);
                }
            }
        }
    }
#undef LOAD_CHUNK
}

// ---------------- edge pass v2: warp per edge, wide loads + 8-lane group reduce ----
__global__ void k_edge_fused(const int* __restrict__ row_index,
                             const int* __restrict__ src_index,
                             const int* __restrict__ org_to_src,
                             const float* __restrict__ dist,
                             const float* __restrict__ src_pos) {
    int e = blockIdx.x * 8 + (threadIdx.x >> 5);
    int lane = threadIdx.x & 31;
    int row = row_index[e];
    int si  = src_index[e];
    int src = org_to_src[si];
    const int4* qr = (const int4*)(g_qkh + (size_t)row * (2 * DD));
    const int4* kr = (const int4*)(g_qkh + (size_t)src * (2 * DD) + DD);
    int4 q1 = qr[lane], q2 = qr[lane + 32];
    int4 k1 = kr[lane], k2 = kr[lane + 32];
    float s1 = dot16(q1, k1);   // head lane>>3
    float s2 = dot16(q2, k2);   // head 4 + (lane>>3)
#pragma unroll
    for (int o = 4; o > 0; o >>= 1) {
        s1 += __shfl_xor_sync(0xffffffffu, s1, o);
        s2 += __shfl_xor_sync(0xffffffffu, s2, o);
    }
    float t1 = __shfl_sync(0xffffffffu, s1, (lane & 3) * 8);
    float t2 = __shfl_sync(0xffffffffu, s2, (lane & 3) * 8);
    if (lane < HH) {
        float cap = (lane < 4) ? t1 : t2;
        float l = cap * 0.125f + g_biasT[(size_t)e * HH + lane];
        float p = __expf(l);
        float d = dist[e];
        float w = (d == 0.0f) ? 0.0f : p / d;
        float sx = src_pos[3 * si + 0];
        float sy = src_pos[3 * si + 1];
        float sz = src_pos[3 * si + 2];
        red_add_v4(&g_featw[(size_t)row * HH + lane], w * sx, w * sy, w * sz, w);
        atomicAdd(&g_den[row * HH + lane], p);
    }
}

// ---------------- node finalize: featw -> mlp_in tail (fp16) + zero pad ----------------
__global__ void k_node_fin(const float* __restrict__ pos) {
    int t = blockIdx.x * blockDim.x + threadIdx.x;
    if (t >= NN * 32) return;
    int n = t >> 5;
    int r = t & 31;
    if (r < 24) {
        int h = r / 3;
        int j = r % 3;
        float4 fw = g_featw[n * HH + h];
        float dn = g_den[n * HH + h];
        float inv = (dn != 0.0f) ? (1.0f / dn) : 0.0f;
        float comp = (j == 0) ? fw.x : ((j == 1) ? fw.y : fw.z);
        float f = comp * inv - fw.w * inv * pos[n * 3 + j];
        g_mlpinh[(size_t)n * MLPIN_P + DD + r] = __float2half(f);
    } else {
        g_mlpinh[(size_t)n * MLPIN_P + DD + r] = __half(0.0f);
    }
}

// ---------------- launch ----------------
extern "C" void kernel_launch(void* const* d_in, const int* in_sizes, int n_in,
                              void* d_out, int out_size) {
    const float* x        = (const float*)d_in[0];
    const float* Wq       = (const float*)d_in[1];
    const float* bq       = (const float*)d_in[2];
    const float* Wk       = (const float*)d_in[3];
    const float* bk       = (const float*)d_in[4];
    const float* g_att    = (const float*)d_in[5];
    const float* b_att    = (const float*)d_in[6];
    const float* g_mlp    = (const float*)d_in[7];
    const float* b_mlp    = (const float*)d_in[8];
    const float* W_in     = (const float*)d_in[9];
    const float* b_in     = (const float*)d_in[10];
    const float* W_out    = (const float*)d_in[11];
    const float* b_out    = (const float*)d_in[12];
    const float* att_bias = (const float*)d_in[13];
    const float* dist     = (const float*)d_in[14];
    const float* pos      = (const float*)d_in[15];
    const float* src_pos  = (const float*)d_in[16];
    const int*   row_index  = (const int*)d_in[17];
    const int*   src_index  = (const int*)d_in[18];
    const int*   org_to_src = (const int*)d_in[19];
    float* out = (float*)d_out;

    __half *pzh, *pmlpinh, *phidh, *pqkh, *pwqkh, *pwinh, *pwouth;
    float* pbqk;
    cudaGetSymbolAddress((void**)&pzh, g_zh);
    cudaGetSymbolAddress((void**)&pmlpinh, g_mlpinh);
    cudaGetSymbolAddress((void**)&phidh, g_hidh);
    cudaGetSymbolAddress((void**)&pqkh, g_qkh);
    cudaGetSymbolAddress((void**)&pwqkh, g_wqkh);
    cudaGetSymbolAddress((void**)&pwinh, g_winh);
    cudaGetSymbolAddress((void**)&pwouth, g_wouth);
    cudaGetSymbolAddress((void**)&pbqk, g_bqk);

    // Side stream + fork/join events. Created once on the first (uncaptured,
    // correctness) call; host-side objects only — no device memory. Every call
    // performs identical work on identical streams (deterministic).
    static cudaStream_t s2 = nullptr;
    static cudaEvent_t evFork = nullptr, evJoin = nullptr;
    if (s2 == nullptr) {
        cudaStreamCreateWithFlags(&s2, cudaStreamNonBlocking);
        cudaEventCreateWithFlags(&evFork, cudaEventDisableTiming);
        cudaEventCreateWithFlags(&evJoin, cudaEventDisableTiming);
    }

    // fork: prep + bias transpose on s2, concurrent with LN on the main stream
    cudaEventRecord(evFork, 0);
    cudaStreamWaitEvent(s2, evFork, 0);
    k_prep<<<(PR6 + 255) / 256, 256, 0, s2>>>(Wq, Wk, W_in, W_out, bq, bk);
    k_tr_bias<<<EE / 32, 256, 0, s2>>>(att_bias);
    cudaEventRecord(evJoin, s2);

    k_ln<<<NN, 128>>>(x, g_att, b_att, g_mlp, b_mlp);

    // join: qk GEMM needs converted weights (s2) and z (main)
    cudaStreamWaitEvent(0, evJoin, 0);
    // [q|k] = z @ [Wq;Wk]^T + [bq;bk]  -> fp16 [N, 1024]
    hmma_gemm<0, 0, 1><<<dim3(2 * DD / 128, NN / 128), 256>>>(
        pzh, pwqkh, pbqk, nullptr, nullptr, pqkh, DD, 2 * DD);
    k_edge_fused<<<EE / 8, 256>>>(row_index, src_index, org_to_src, dist, src_pos);
    k_node_fin<<<(NN * 32 + 255) / 256, 256>>>(pos);
    // hid = gelu(mlpin @ W_in^T + b_in) -> fp16
    hmma_gemm<1, 0, 1><<<dim3(HID / 128, NN / 128), 256>>>(
        pmlpinh, pwinh, b_in, nullptr, nullptr, phidh, MLPIN_P, HID);
    // out = x + hid @ W_out^T + b_out -> fp32
    hmma_gemm<0, 1, 0><<<dim3(DD / 128, NN / 128), 256>>>(
        phidh, pwouth, b_out, x, out, nullptr, HID, DD);
}